// round 1
// baseline (speedup 1.0000x reference)
#include <cuda_runtime.h>
#include <cuda_bf16.h>
#include <cstdint>

// Problem constants
#define N_APP  100000
#define N_ATTR 50000
#define NEDGE  500000
#define D      128

// ---------------- device scratch (no allocation allowed) ----------------
__device__ float g_n0[(size_t)N_ATTR * D];   // agg rel0 (app->attr)
__device__ float g_n1[(size_t)N_APP * D];    // agg rel1 (attr->app)
__device__ float g_n2[(size_t)N_APP * D];    // agg rel2 (app->app)
__device__ float g_hattr[(size_t)N_ATTR * D];
__device__ float g_happ[(size_t)N_APP * D];
__device__ float g_deg0[N_ATTR];
__device__ float g_deg1[N_APP];
__device__ float g_deg2[N_APP];
__device__ float g_pattr[(size_t)N_ATTR * 2];  // h_attr @ Wn1c
__device__ float g_papp[(size_t)N_APP * 4];    // h_app @ [Wsc | Wn2c]
__device__ float g_q1[(size_t)N_APP * 2];
__device__ float g_q2[(size_t)N_APP * 2];
__device__ float g_Wsum1[D * D];   // Wself1[1]+Wself1[2]
__device__ float g_bsum1[D];       // b1[1]+b1[2]
__device__ float g_Wn1c[D * 2];    // Wneigh2[1] @ Wc
__device__ float g_Wapp4[D * 4];   // cols 0..1: (Wself2[1]+Wself2[2])@Wc ; cols 2..3: Wneigh2[2]@Wc
__device__ float g_bce[2];         // (b2[1]+b2[2])@Wc + bc

// ---------------- helpers ----------------
__device__ __forceinline__ void red_add_v4(float* addr, float4 v) {
    asm volatile("red.global.add.v4.f32 [%0], {%1,%2,%3,%4};"
                 :: "l"(addr), "f"(v.x), "f"(v.y), "f"(v.z), "f"(v.w) : "memory");
}
__device__ __forceinline__ void red_add_v2(float* addr, float a, float b) {
    asm volatile("red.global.add.v2.f32 [%0], {%1,%2};"
                 :: "l"(addr), "f"(a), "f"(b) : "memory");
}

// ---------------- tiny weight-prep kernel (1 block, 256 thr) ----------------
__global__ void prep_kernel(const float* __restrict__ Wself1, const float* __restrict__ b1,
                            const float* __restrict__ Wself2, const float* __restrict__ Wneigh2,
                            const float* __restrict__ b2,
                            const float* __restrict__ Wc, const float* __restrict__ bc)
{
    int tid = threadIdx.x;
    for (int i = tid; i < D * D; i += 256)
        g_Wsum1[i] = Wself1[16384 + i] + Wself1[32768 + i];
    if (tid < D) g_bsum1[tid] = b1[128 + tid] + b1[256 + tid];
    {
        int i = tid >> 1, j = tid & 1;
        float s_sc = 0.f, s_n2 = 0.f, s_n1 = 0.f;
        #pragma unroll 4
        for (int l = 0; l < D; l++) {
            float wc = Wc[l * 2 + j];
            s_sc += (Wself2[16384 + i * D + l] + Wself2[32768 + i * D + l]) * wc;
            s_n2 += Wneigh2[32768 + i * D + l] * wc;
            s_n1 += Wneigh2[16384 + i * D + l] * wc;
        }
        g_Wapp4[i * 4 + j]     = s_sc;
        g_Wapp4[i * 4 + 2 + j] = s_n2;
        g_Wn1c[i * 2 + j]      = s_n1;
    }
    if (tid < 2) {
        float s = bc[tid];
        for (int l = 0; l < D; l++) s += (b2[128 + l] + b2[256 + l]) * Wc[l * 2 + tid];
        g_bce[tid] = s;
    }
}

// ---------------- edge scatter: warp per edge, 128 floats = 32 x float4 ----------------
__global__ void __launch_bounds__(256) scatter_feat(
    const float4* __restrict__ feat, const int* __restrict__ src, const int* __restrict__ dst,
    const float* __restrict__ ew, float4* __restrict__ accum, float* __restrict__ deg, int E)
{
    int warp = (blockIdx.x * 256 + threadIdx.x) >> 5;
    int lane = threadIdx.x & 31;
    if (warp >= E) return;
    int   s = __ldg(&src[warp]);
    int   d = __ldg(&dst[warp]);
    float w = __ldg(&ew[warp]);
    float4 v = feat[(size_t)s * 32 + lane];
    v.x *= w; v.y *= w; v.z *= w; v.w *= w;
    red_add_v4((float*)(accum + (size_t)d * 32 + lane), v);
    if (lane == 0) atomicAdd(deg + d, 1.0f);
}

// ---------------- fused multi-input SGEMM: C[M,128] = sum_b scale_b(A_b) @ B_b + bias, opt relu
// 128x128 tile, BK=8, 256 threads, 8x8 microtile. Per-row 1/max(deg,1) scaling folded into A load.
__global__ void __launch_bounds__(256) gemm_fused(
    const float* __restrict__ A0, const float* __restrict__ dg0, const float* __restrict__ B0,
    const float* __restrict__ A1, const float* __restrict__ dg1, const float* __restrict__ B1,
    const float* __restrict__ A2, const float* __restrict__ dg2, const float* __restrict__ B2,
    const float* __restrict__ bias, float* __restrict__ C, int M, int do_relu)
{
    __shared__ float As[8][128];
    __shared__ float Bs[8][128];
    const int tid = threadIdx.x;
    const int m0 = blockIdx.x * 128;
    const int ty = tid >> 4, tx = tid & 15;
    const int aRow = tid >> 1, aCol = (tid & 1) << 2;
    const int bRow = tid >> 5, bCol = (tid & 31) << 2;
    const int gRow = m0 + aRow;
    const bool rowOK = (gRow < M);

    float acc[8][8];
    #pragma unroll
    for (int i = 0; i < 8; i++)
        #pragma unroll
        for (int j = 0; j < 8; j++) acc[i][j] = 0.f;

    const float* Aps[3] = {A0, A1, A2};
    const float* Bps[3] = {B0, B1, B2};
    const float* Dps[3] = {dg0, dg1, dg2};

    for (int blk = 0; blk < 3; blk++) {
        const float* A = Aps[blk];
        if (A == nullptr) break;
        const float* B = Bps[blk];
        const float* dgp = Dps[blk];
        float scale = 1.0f;
        if (dgp != nullptr && rowOK) scale = 1.0f / fmaxf(dgp[gRow], 1.0f);

        #pragma unroll 1
        for (int k0 = 0; k0 < 128; k0 += 8) {
            float4 av = make_float4(0.f, 0.f, 0.f, 0.f);
            if (rowOK) av = *reinterpret_cast<const float4*>(A + (size_t)gRow * 128 + k0 + aCol);
            av.x *= scale; av.y *= scale; av.z *= scale; av.w *= scale;
            float4 bv = *reinterpret_cast<const float4*>(B + (size_t)(k0 + bRow) * 128 + bCol);
            __syncthreads();
            As[aCol + 0][aRow] = av.x;
            As[aCol + 1][aRow] = av.y;
            As[aCol + 2][aRow] = av.z;
            As[aCol + 3][aRow] = av.w;
            *reinterpret_cast<float4*>(&Bs[bRow][bCol]) = bv;
            __syncthreads();
            #pragma unroll
            for (int kk = 0; kk < 8; kk++) {
                float a[8], b[8];
                #pragma unroll
                for (int i = 0; i < 8; i++) a[i] = As[kk][ty * 8 + i];
                #pragma unroll
                for (int j = 0; j < 8; j++) b[j] = Bs[kk][tx * 8 + j];
                #pragma unroll
                for (int i = 0; i < 8; i++)
                    #pragma unroll
                    for (int j = 0; j < 8; j++) acc[i][j] += a[i] * b[j];
            }
        }
    }

    #pragma unroll
    for (int i = 0; i < 8; i++) {
        int row = m0 + ty * 8 + i;
        if (row >= M) continue;
        #pragma unroll
        for (int j = 0; j < 8; j++) {
            float v = acc[i][j] + bias[tx * 8 + j];
            if (do_relu) v = fmaxf(v, 0.f);
            C[(size_t)row * 128 + tx * 8 + j] = v;
        }
    }
}

// ---------------- projection: P[M,NC] = H[M,128] @ W[128,NC]  (warp per row) ----------------
template <int NC>
__global__ void __launch_bounds__(256) proj_kernel(const float4* __restrict__ H,
                                                   const float* __restrict__ W,
                                                   float* __restrict__ P, int M)
{
    __shared__ float Ws[128 * NC];
    for (int i = threadIdx.x; i < 128 * NC; i += 256) Ws[i] = W[i];
    __syncthreads();
    int warp = (blockIdx.x * 256 + threadIdx.x) >> 5;
    int lane = threadIdx.x & 31;
    if (warp >= M) return;
    float4 h = H[(size_t)warp * 32 + lane];
    int k = lane * 4;
    float acc[NC];
    #pragma unroll
    for (int c = 0; c < NC; c++)
        acc[c] = h.x * Ws[(k + 0) * NC + c] + h.y * Ws[(k + 1) * NC + c]
               + h.z * Ws[(k + 2) * NC + c] + h.w * Ws[(k + 3) * NC + c];
    #pragma unroll
    for (int c = 0; c < NC; c++)
        #pragma unroll
        for (int o = 16; o > 0; o >>= 1) acc[c] += __shfl_xor_sync(0xffffffffu, acc[c], o);
    if (lane == 0) {
        #pragma unroll
        for (int c = 0; c < NC; c++) P[(size_t)warp * NC + c] = acc[c];
    }
}

// ---------------- 2-wide edge scatter on projected features ----------------
__global__ void __launch_bounds__(256) scatter_proj(
    const float* __restrict__ P, int stride, int off,
    const int* __restrict__ src, const int* __restrict__ dst, const float* __restrict__ ew,
    float* __restrict__ Q, int E)
{
    int e = blockIdx.x * 256 + threadIdx.x;
    if (e >= E) return;
    int s = src[e], d = dst[e];
    float w = ew[e];
    float a = P[(size_t)s * stride + off]     * w;
    float b = P[(size_t)s * stride + off + 1] * w;
    red_add_v2(Q + (size_t)d * 2, a, b);
}

// ---------------- finalize: out = p_self + q1/deg1 + q2/deg2 + bce ----------------
__global__ void __launch_bounds__(256) finalize_kernel(float* __restrict__ out)
{
    int v = blockIdx.x * 256 + threadIdx.x;
    if (v >= N_APP) return;
    float i1 = 1.0f / fmaxf(g_deg1[v], 1.0f);
    float i2 = 1.0f / fmaxf(g_deg2[v], 1.0f);
    out[v * 2 + 0] = g_papp[v * 4 + 0] + g_q1[v * 2 + 0] * i1 + g_q2[v * 2 + 0] * i2 + g_bce[0];
    out[v * 2 + 1] = g_papp[v * 4 + 1] + g_q1[v * 2 + 1] * i1 + g_q2[v * 2 + 1] * i2 + g_bce[1];
}

// ---------------- launch ----------------
extern "C" void kernel_launch(void* const* d_in, const int* in_sizes, int n_in,
                              void* d_out, int out_size)
{
    const float* x_app   = (const float*)d_in[0];
    const float* x_attr  = (const float*)d_in[1];
    const float* ew0     = (const float*)d_in[2];
    const float* ew1     = (const float*)d_in[3];
    const float* ew2     = (const float*)d_in[4];
    const float* Wself1  = (const float*)d_in[5];
    const float* Wneigh1 = (const float*)d_in[6];
    const float* b1      = (const float*)d_in[7];
    const float* Wself2  = (const float*)d_in[8];
    const float* Wneigh2 = (const float*)d_in[9];
    const float* b2      = (const float*)d_in[10];
    const float* Wc      = (const float*)d_in[11];
    const float* bc      = (const float*)d_in[12];
    const int* src0 = (const int*)d_in[13];
    const int* dst0 = (const int*)d_in[14];
    const int* src1 = (const int*)d_in[15];
    const int* dst1 = (const int*)d_in[16];
    const int* src2 = (const int*)d_in[17];
    const int* dst2 = (const int*)d_in[18];
    float* out = (float*)d_out;
    const int E = in_sizes[2];

    // resolve scratch addresses
    float *n0, *n1, *n2, *hattr, *happ, *deg0, *deg1, *deg2, *pattr, *papp, *q1, *q2;
    float *Wsum1, *bsum1, *Wn1c, *Wapp4;
    cudaGetSymbolAddress((void**)&n0, g_n0);
    cudaGetSymbolAddress((void**)&n1, g_n1);
    cudaGetSymbolAddress((void**)&n2, g_n2);
    cudaGetSymbolAddress((void**)&hattr, g_hattr);
    cudaGetSymbolAddress((void**)&happ, g_happ);
    cudaGetSymbolAddress((void**)&deg0, g_deg0);
    cudaGetSymbolAddress((void**)&deg1, g_deg1);
    cudaGetSymbolAddress((void**)&deg2, g_deg2);
    cudaGetSymbolAddress((void**)&pattr, g_pattr);
    cudaGetSymbolAddress((void**)&papp, g_papp);
    cudaGetSymbolAddress((void**)&q1, g_q1);
    cudaGetSymbolAddress((void**)&q2, g_q2);
    cudaGetSymbolAddress((void**)&Wsum1, g_Wsum1);
    cudaGetSymbolAddress((void**)&bsum1, g_bsum1);
    cudaGetSymbolAddress((void**)&Wn1c, g_Wn1c);
    cudaGetSymbolAddress((void**)&Wapp4, g_Wapp4);

    // zero accumulators (memset nodes are graph-capturable)
    cudaMemsetAsync(n0, 0, sizeof(g_n0), 0);
    cudaMemsetAsync(n1, 0, sizeof(g_n1), 0);
    cudaMemsetAsync(n2, 0, sizeof(g_n2), 0);
    cudaMemsetAsync(deg0, 0, sizeof(g_deg0), 0);
    cudaMemsetAsync(deg1, 0, sizeof(g_deg1), 0);
    cudaMemsetAsync(deg2, 0, sizeof(g_deg2), 0);
    cudaMemsetAsync(q1, 0, sizeof(g_q1), 0);
    cudaMemsetAsync(q2, 0, sizeof(g_q2), 0);

    // effective-weight precompute (layer-2 folding through Wc)
    prep_kernel<<<1, 256>>>(Wself1, b1, Wself2, Wneigh2, b2, Wc, bc);

    // layer-1 aggregations (warp per edge)
    int sblocks = (E * 32 + 255) / 256;
    scatter_feat<<<sblocks, 256>>>((const float4*)x_app,  src0, dst0, ew0, (float4*)n0, deg0, E);
    scatter_feat<<<sblocks, 256>>>((const float4*)x_attr, src1, dst1, ew1, (float4*)n1, deg1, E);
    scatter_feat<<<sblocks, 256>>>((const float4*)x_app,  src2, dst2, ew2, (float4*)n2, deg2, E);

    // layer-1 GEMMs (self weights folded, deg division folded into A load)
    gemm_fused<<<(N_ATTR + 127) / 128, 256>>>(
        x_attr, nullptr, Wself1,            // self term, Wself1[0]
        n0, deg0, Wneigh1,                  // neighbor term, Wneigh1[0]
        nullptr, nullptr, nullptr,
        b1, hattr, N_ATTR, 1);
    gemm_fused<<<(N_APP + 127) / 128, 256>>>(
        x_app, nullptr, Wsum1,              // self term, Wself1[1]+Wself1[2]
        n1, deg1, Wneigh1 + 16384,          // rel1 neighbor
        n2, deg2, Wneigh1 + 32768,          // rel2 neighbor
        bsum1, happ, N_APP, 1);

    // layer 2 folded to 2-dim projections
    proj_kernel<2><<<(N_ATTR * 32 + 255) / 256, 256>>>((const float4*)hattr, Wn1c, pattr, N_ATTR);
    proj_kernel<4><<<(N_APP * 32 + 255) / 256, 256>>>((const float4*)happ, Wapp4, papp, N_APP);

    // layer-2 aggregation on 2-dim projected features
    int eblocks = (E + 255) / 256;
    scatter_proj<<<eblocks, 256>>>(pattr, 2, 0, src1, dst1, ew1, q1, E);
    scatter_proj<<<eblocks, 256>>>(papp,  4, 2, src2, dst2, ew2, q2, E);

    finalize_kernel<<<(N_APP + 255) / 256, 256>>>(out);
}

// round 2
// speedup vs baseline: 1.0844x; 1.0844x over previous
#include <cuda_runtime.h>
#include <cuda_bf16.h>
#include <cstdint>

// Problem constants
#define N_APP  100000
#define N_ATTR 50000
#define NEDGE  500000
#define D      128

// ---------------- device scratch (no allocation allowed) ----------------
__device__ float g_n0[(size_t)N_ATTR * D];   // agg rel0 (app->attr)
__device__ float g_n1[(size_t)N_APP * D];    // agg rel1 (attr->app)
__device__ float g_n2[(size_t)N_APP * D];    // agg rel2 (app->app)
__device__ float g_hattr[(size_t)N_ATTR * D];
__device__ float g_happ[(size_t)N_APP * D];
__device__ float g_deg0[N_ATTR];
__device__ float g_deg1[N_APP];
__device__ float g_deg2[N_APP];
__device__ float g_pattr[(size_t)N_ATTR * 2];  // h_attr @ Wn1c
__device__ float g_papp[(size_t)N_APP * 4];    // h_app @ [Wsc | Wn2c]
__device__ float g_q1[(size_t)N_APP * 2];
__device__ float g_q2[(size_t)N_APP * 2];
__device__ float g_Wsum1[D * D];   // Wself1[1]+Wself1[2]
__device__ float g_bsum1[D];       // b1[1]+b1[2]
__device__ float g_Wn1c[D * 2];    // Wneigh2[1] @ Wc
__device__ float g_Wapp4[D * 4];   // cols 0..1: (Wself2[1]+Wself2[2])@Wc ; cols 2..3: Wneigh2[2]@Wc
__device__ float g_bce[2];         // (b2[1]+b2[2])@Wc + bc

// ---------------- helpers ----------------
__device__ __forceinline__ void red_add_v4(float* addr, float4 v) {
    asm volatile("red.global.add.v4.f32 [%0], {%1,%2,%3,%4};"
                 :: "l"(addr), "f"(v.x), "f"(v.y), "f"(v.z), "f"(v.w) : "memory");
}
__device__ __forceinline__ void red_add_v2(float* addr, float a, float b) {
    asm volatile("red.global.add.v2.f32 [%0], {%1,%2};"
                 :: "l"(addr), "f"(a), "f"(b) : "memory");
}
__device__ __forceinline__ unsigned long long pack_dup(float a) {
    unsigned long long r;
    asm("mov.b64 %0, {%1, %1};" : "=l"(r) : "f"(a));
    return r;
}
__device__ __forceinline__ float2 unpack_f2(unsigned long long p) {
    float2 r;
    asm("mov.b64 {%0, %1}, %2;" : "=f"(r.x), "=f"(r.y) : "l"(p));
    return r;
}
__device__ __forceinline__ void ffma2(unsigned long long& acc, unsigned long long a, unsigned long long b) {
    asm("fma.rn.f32x2 %0, %1, %2, %0;" : "+l"(acc) : "l"(a), "l"(b));
}

// ---------------- tiny weight-prep kernel (1 block, 256 thr) ----------------
__global__ void prep_kernel(const float* __restrict__ Wself1, const float* __restrict__ b1,
                            const float* __restrict__ Wself2, const float* __restrict__ Wneigh2,
                            const float* __restrict__ b2,
                            const float* __restrict__ Wc, const float* __restrict__ bc)
{
    int tid = threadIdx.x;
    for (int i = tid; i < D * D; i += 256)
        g_Wsum1[i] = Wself1[16384 + i] + Wself1[32768 + i];
    if (tid < D) g_bsum1[tid] = b1[128 + tid] + b1[256 + tid];
    {
        int i = tid >> 1, j = tid & 1;
        float s_sc = 0.f, s_n2 = 0.f, s_n1 = 0.f;
        #pragma unroll 4
        for (int l = 0; l < D; l++) {
            float wc = Wc[l * 2 + j];
            s_sc += (Wself2[16384 + i * D + l] + Wself2[32768 + i * D + l]) * wc;
            s_n2 += Wneigh2[32768 + i * D + l] * wc;
            s_n1 += Wneigh2[16384 + i * D + l] * wc;
        }
        g_Wapp4[i * 4 + j]     = s_sc;
        g_Wapp4[i * 4 + 2 + j] = s_n2;
        g_Wn1c[i * 2 + j]      = s_n1;
    }
    if (tid < 2) {
        float s = bc[tid];
        for (int l = 0; l < D; l++) s += (b2[128 + l] + b2[256 + l]) * Wc[l * 2 + tid];
        g_bce[tid] = s;
    }
}

// ---------------- edge scatter: warp per 8 edges, batched index loads + MLP-8 gathers ----------------
__global__ void __launch_bounds__(256) scatter_feat(
    const float4* __restrict__ feat, const int* __restrict__ src, const int* __restrict__ dst,
    const float* __restrict__ ew, float4* __restrict__ accum, float* __restrict__ deg, int E)
{
    int warp = (blockIdx.x * 256 + threadIdx.x) >> 5;
    int lane = threadIdx.x & 31;
    int e0 = warp * 8;
    if (e0 >= E) return;
    int n = E - e0; if (n > 8) n = 8;

    int s_ = 0, d_ = 0; float w_ = 0.f;
    if (lane < n) {
        s_ = __ldg(&src[e0 + lane]);
        d_ = __ldg(&dst[e0 + lane]);
        w_ = __ldg(&ew[e0 + lane]);
    }

    // issue all gathers first (MLP)
    float4 v[8];
    #pragma unroll
    for (int i = 0; i < 8; i++) {
        int s = __shfl_sync(0xffffffffu, s_, i);
        if (i < n) v[i] = feat[(size_t)s * 32 + lane];
    }
    // then all reductions
    #pragma unroll
    for (int i = 0; i < 8; i++) {
        int d   = __shfl_sync(0xffffffffu, d_, i);
        float w = __shfl_sync(0xffffffffu, w_, i);
        if (i < n) {
            float4 t = v[i];
            t.x *= w; t.y *= w; t.z *= w; t.w *= w;
            red_add_v4((float*)(accum + (size_t)d * 32 + lane), t);
        }
    }
    if (lane < n) atomicAdd(deg + d_, 1.0f);
}

// ---------------- fused multi-input SGEMM with packed fma.rn.f32x2 ----------------
// C[M,128] = sum_b scale_b(A_b) @ B_b + bias, opt relu.
// 128x128 tile, BK=8, 256 threads, 8x8 microtile computed as 8x4 float2 pairs.
__global__ void __launch_bounds__(256, 2) gemm_fused(
    const float* __restrict__ A0, const float* __restrict__ dg0, const float* __restrict__ B0,
    const float* __restrict__ A1, const float* __restrict__ dg1, const float* __restrict__ B1,
    const float* __restrict__ A2, const float* __restrict__ dg2, const float* __restrict__ B2,
    const float* __restrict__ bias, float* __restrict__ C, int M, int do_relu)
{
    __shared__ float As[8][128];
    __shared__ float Bs[8][128];
    const int tid = threadIdx.x;
    const int m0 = blockIdx.x * 128;
    const int ty = tid >> 4, tx = tid & 15;
    const int aRow = tid >> 1, aCol = (tid & 1) << 2;
    const int bRow = tid >> 5, bCol = (tid & 31) << 2;
    const int gRow = m0 + aRow;
    const bool rowOK = (gRow < M);

    unsigned long long accp[8][4];
    #pragma unroll
    for (int i = 0; i < 8; i++)
        #pragma unroll
        for (int j = 0; j < 4; j++) accp[i][j] = 0ull;

    const float* Aps[3] = {A0, A1, A2};
    const float* Bps[3] = {B0, B1, B2};
    const float* Dps[3] = {dg0, dg1, dg2};

    for (int blk = 0; blk < 3; blk++) {
        const float* A = Aps[blk];
        if (A == nullptr) break;
        const float* B = Bps[blk];
        const float* dgp = Dps[blk];
        float scale = 1.0f;
        if (dgp != nullptr && rowOK) scale = 1.0f / fmaxf(dgp[gRow], 1.0f);

        #pragma unroll 1
        for (int k0 = 0; k0 < 128; k0 += 8) {
            float4 av = make_float4(0.f, 0.f, 0.f, 0.f);
            if (rowOK) av = *reinterpret_cast<const float4*>(A + (size_t)gRow * 128 + k0 + aCol);
            av.x *= scale; av.y *= scale; av.z *= scale; av.w *= scale;
            float4 bv = *reinterpret_cast<const float4*>(B + (size_t)(k0 + bRow) * 128 + bCol);
            __syncthreads();
            As[aCol + 0][aRow] = av.x;
            As[aCol + 1][aRow] = av.y;
            As[aCol + 2][aRow] = av.z;
            As[aCol + 3][aRow] = av.w;
            *reinterpret_cast<float4*>(&Bs[bRow][bCol]) = bv;
            __syncthreads();
            #pragma unroll
            for (int kk = 0; kk < 8; kk++) {
                unsigned long long bp[4];
                const unsigned long long* brow =
                    reinterpret_cast<const unsigned long long*>(&Bs[kk][tx * 8]);
                #pragma unroll
                for (int j = 0; j < 4; j++) bp[j] = brow[j];
                unsigned long long ap[8];
                #pragma unroll
                for (int i = 0; i < 8; i++) ap[i] = pack_dup(As[kk][ty * 8 + i]);
                #pragma unroll
                for (int i = 0; i < 8; i++)
                    #pragma unroll
                    for (int j = 0; j < 4; j++) ffma2(accp[i][j], ap[i], bp[j]);
            }
        }
    }

    #pragma unroll
    for (int i = 0; i < 8; i++) {
        int row = m0 + ty * 8 + i;
        if (row >= M) continue;
        #pragma unroll
        for (int j = 0; j < 4; j++) {
            float2 r = unpack_f2(accp[i][j]);
            float v0 = r.x + bias[tx * 8 + 2 * j + 0];
            float v1 = r.y + bias[tx * 8 + 2 * j + 1];
            if (do_relu) { v0 = fmaxf(v0, 0.f); v1 = fmaxf(v1, 0.f); }
            *reinterpret_cast<float2*>(&C[(size_t)row * 128 + tx * 8 + 2 * j]) = make_float2(v0, v1);
        }
    }
}

// ---------------- projection: P[M,NC] = H[M,128] @ W[128,NC]  (warp per row) ----------------
template <int NC>
__global__ void __launch_bounds__(256) proj_kernel(const float4* __restrict__ H,
                                                   const float* __restrict__ W,
                                                   float* __restrict__ P, int M)
{
    __shared__ float Ws[128 * NC];
    for (int i = threadIdx.x; i < 128 * NC; i += 256) Ws[i] = W[i];
    __syncthreads();
    int warp = (blockIdx.x * 256 + threadIdx.x) >> 5;
    int lane = threadIdx.x & 31;
    if (warp >= M) return;
    float4 h = H[(size_t)warp * 32 + lane];
    int k = lane * 4;
    float acc[NC];
    #pragma unroll
    for (int c = 0; c < NC; c++)
        acc[c] = h.x * Ws[(k + 0) * NC + c] + h.y * Ws[(k + 1) * NC + c]
               + h.z * Ws[(k + 2) * NC + c] + h.w * Ws[(k + 3) * NC + c];
    #pragma unroll
    for (int c = 0; c < NC; c++)
        #pragma unroll
        for (int o = 16; o > 0; o >>= 1) acc[c] += __shfl_xor_sync(0xffffffffu, acc[c], o);
    if (lane == 0) {
        #pragma unroll
        for (int c = 0; c < NC; c++) P[(size_t)warp * NC + c] = acc[c];
    }
}

// ---------------- 2-wide edge scatter on projected features ----------------
__global__ void __launch_bounds__(256) scatter_proj(
    const float* __restrict__ P, int stride, int off,
    const int* __restrict__ src, const int* __restrict__ dst, const float* __restrict__ ew,
    float* __restrict__ Q, int E)
{
    int e = blockIdx.x * 256 + threadIdx.x;
    if (e >= E) return;
    int s = src[e], d = dst[e];
    float w = ew[e];
    float a = P[(size_t)s * stride + off]     * w;
    float b = P[(size_t)s * stride + off + 1] * w;
    red_add_v2(Q + (size_t)d * 2, a, b);
}

// ---------------- finalize: out = p_self + q1/deg1 + q2/deg2 + bce ----------------
__global__ void __launch_bounds__(256) finalize_kernel(float* __restrict__ out)
{
    int v = blockIdx.x * 256 + threadIdx.x;
    if (v >= N_APP) return;
    float i1 = 1.0f / fmaxf(g_deg1[v], 1.0f);
    float i2 = 1.0f / fmaxf(g_deg2[v], 1.0f);
    out[v * 2 + 0] = g_papp[v * 4 + 0] + g_q1[v * 2 + 0] * i1 + g_q2[v * 2 + 0] * i2 + g_bce[0];
    out[v * 2 + 1] = g_papp[v * 4 + 1] + g_q1[v * 2 + 1] * i1 + g_q2[v * 2 + 1] * i2 + g_bce[1];
}

// ---------------- launch ----------------
extern "C" void kernel_launch(void* const* d_in, const int* in_sizes, int n_in,
                              void* d_out, int out_size)
{
    const float* x_app   = (const float*)d_in[0];
    const float* x_attr  = (const float*)d_in[1];
    const float* ew0     = (const float*)d_in[2];
    const float* ew1     = (const float*)d_in[3];
    const float* ew2     = (const float*)d_in[4];
    const float* Wself1  = (const float*)d_in[5];
    const float* Wneigh1 = (const float*)d_in[6];
    const float* b1      = (const float*)d_in[7];
    const float* Wself2  = (const float*)d_in[8];
    const float* Wneigh2 = (const float*)d_in[9];
    const float* b2      = (const float*)d_in[10];
    const float* Wc      = (const float*)d_in[11];
    const float* bc      = (const float*)d_in[12];
    const int* src0 = (const int*)d_in[13];
    const int* dst0 = (const int*)d_in[14];
    const int* src1 = (const int*)d_in[15];
    const int* dst1 = (const int*)d_in[16];
    const int* src2 = (const int*)d_in[17];
    const int* dst2 = (const int*)d_in[18];
    float* out = (float*)d_out;
    const int E = in_sizes[2];

    // resolve scratch addresses
    float *n0, *n1, *n2, *hattr, *happ, *deg0, *deg1, *deg2, *pattr, *papp, *q1, *q2;
    float *Wsum1, *bsum1, *Wn1c, *Wapp4;
    cudaGetSymbolAddress((void**)&n0, g_n0);
    cudaGetSymbolAddress((void**)&n1, g_n1);
    cudaGetSymbolAddress((void**)&n2, g_n2);
    cudaGetSymbolAddress((void**)&hattr, g_hattr);
    cudaGetSymbolAddress((void**)&happ, g_happ);
    cudaGetSymbolAddress((void**)&deg0, g_deg0);
    cudaGetSymbolAddress((void**)&deg1, g_deg1);
    cudaGetSymbolAddress((void**)&deg2, g_deg2);
    cudaGetSymbolAddress((void**)&pattr, g_pattr);
    cudaGetSymbolAddress((void**)&papp, g_papp);
    cudaGetSymbolAddress((void**)&q1, g_q1);
    cudaGetSymbolAddress((void**)&q2, g_q2);
    cudaGetSymbolAddress((void**)&Wsum1, g_Wsum1);
    cudaGetSymbolAddress((void**)&bsum1, g_bsum1);
    cudaGetSymbolAddress((void**)&Wn1c, g_Wn1c);
    cudaGetSymbolAddress((void**)&Wapp4, g_Wapp4);

    // zero accumulators (memset nodes are graph-capturable)
    cudaMemsetAsync(n0, 0, sizeof(g_n0), 0);
    cudaMemsetAsync(n1, 0, sizeof(g_n1), 0);
    cudaMemsetAsync(n2, 0, sizeof(g_n2), 0);
    cudaMemsetAsync(deg0, 0, sizeof(g_deg0), 0);
    cudaMemsetAsync(deg1, 0, sizeof(g_deg1), 0);
    cudaMemsetAsync(deg2, 0, sizeof(g_deg2), 0);
    cudaMemsetAsync(q1, 0, sizeof(g_q1), 0);
    cudaMemsetAsync(q2, 0, sizeof(g_q2), 0);

    // effective-weight precompute (layer-2 folding through Wc)
    prep_kernel<<<1, 256>>>(Wself1, b1, Wself2, Wneigh2, b2, Wc, bc);

    // layer-1 aggregations (warp per 8 edges)
    int sblocks = (E + 63) / 64;
    scatter_feat<<<sblocks, 256>>>((const float4*)x_app,  src0, dst0, ew0, (float4*)n0, deg0, E);
    scatter_feat<<<sblocks, 256>>>((const float4*)x_attr, src1, dst1, ew1, (float4*)n1, deg1, E);
    scatter_feat<<<sblocks, 256>>>((const float4*)x_app,  src2, dst2, ew2, (float4*)n2, deg2, E);

    // layer-1 GEMMs (self weights folded, deg division folded into A load)
    gemm_fused<<<(N_ATTR + 127) / 128, 256>>>(
        x_attr, nullptr, Wself1,            // self term, Wself1[0]
        n0, deg0, Wneigh1,                  // neighbor term, Wneigh1[0]
        nullptr, nullptr, nullptr,
        b1, hattr, N_ATTR, 1);
    gemm_fused<<<(N_APP + 127) / 128, 256>>>(
        x_app, nullptr, Wsum1,              // self term, Wself1[1]+Wself1[2]
        n1, deg1, Wneigh1 + 16384,          // rel1 neighbor
        n2, deg2, Wneigh1 + 32768,          // rel2 neighbor
        bsum1, happ, N_APP, 1);

    // layer 2 folded to 2-dim projections
    proj_kernel<2><<<(N_ATTR * 32 + 255) / 256, 256>>>((const float4*)hattr, Wn1c, pattr, N_ATTR);
    proj_kernel<4><<<(N_APP * 32 + 255) / 256, 256>>>((const float4*)happ, Wapp4, papp, N_APP);

    // layer-2 aggregation on 2-dim projected features
    int eblocks = (E + 255) / 256;
    scatter_proj<<<eblocks, 256>>>(pattr, 2, 0, src1, dst1, ew1, q1, E);
    scatter_proj<<<eblocks, 256>>>(papp,  4, 2, src2, dst2, ew2, q2, E);

    finalize_kernel<<<(N_APP + 255) / 256, 256>>>(out);
}